// round 16
// baseline (speedup 1.0000x reference)
#include <cuda_runtime.h>
#include <cuda_bf16.h>
#include <math.h>

// Problem constants
#define Bq   8
#define Nq   1024
#define Iq   64
#define Eq   2
#define Hq   2
#define Dq   128
#define Oq   64
#define EHq  4
#define ROWS (Bq*Nq)        // 8192
#define IN1q (Eq*Hq*Dq)     // 512

// ---------------- scratch (device globals; no cudaMalloc allowed) ----------
__device__ float g_s1    [EHq*ROWS];
__device__ float g_s2    [EHq*ROWS];
__device__ float g_cs    [EHq*ROWS];      // colsum, then -ln(colsum)
__device__ float g_state2[ROWS*Dq];
__device__ __nv_bfloat16 g_A0hi[ROWS*Dq],   g_A0lo[ROWS*Dq];
__device__ __nv_bfloat16 g_A1hi[ROWS*IN1q], g_A1lo[ROWS*IN1q];
__device__ __nv_bfloat16 g_Wshi[EHq*IN1q*Dq], g_Wslo[EHq*IN1q*Dq];
__device__ __nv_bfloat16 g_Vhi [EHq*ROWS*Dq], g_Vlo [EHq*ROWS*Dq];

// ---------------- helpers ---------------------------------------------------
__device__ __forceinline__ unsigned su32(const void* p) {
    return (unsigned)__cvta_generic_to_shared(p);
}
__device__ __forceinline__ void cpa16(void* dst, const void* src) {
    asm volatile("cp.async.cg.shared.global [%0], [%1], 16;"
                 :: "r"(su32(dst)), "l"(src));
}
#define CPA_COMMIT asm volatile("cp.async.commit_group;")
#define CPA_WAIT1  asm volatile("cp.async.wait_group 1;")
#define CPA_WAIT0  asm volatile("cp.async.wait_group 0;")

#define LDMX4(r0,r1,r2,r3,addr) \
    asm volatile("ldmatrix.sync.aligned.m8n8.x4.shared.b16 {%0,%1,%2,%3}, [%4];" \
        : "=r"(r0),"=r"(r1),"=r"(r2),"=r"(r3) : "r"(addr))
#define LDMX4T(r0,r1,r2,r3,addr) \
    asm volatile("ldmatrix.sync.aligned.m8n8.x4.trans.shared.b16 {%0,%1,%2,%3}, [%4];" \
        : "=r"(r0),"=r"(r1),"=r"(r2),"=r"(r3) : "r"(addr))
#define MMA(c,a,b0,b1) \
    asm volatile("mma.sync.aligned.m16n8k16.row.col.f32.bf16.bf16.f32 " \
        "{%0,%1,%2,%3}, {%4,%5,%6,%7}, {%8,%9}, {%0,%1,%2,%3};" \
        : "+f"((c)[0]),"+f"((c)[1]),"+f"((c)[2]),"+f"((c)[3]) \
        : "r"((a)[0]),"r"((a)[1]),"r"((a)[2]),"r"((a)[3]), "r"(b0),"r"(b1))

__device__ __forceinline__ void bsplit(float x, __nv_bfloat16& hi, __nv_bfloat16& lo) {
    hi = __float2bfloat16(x);
    lo = __float2bfloat16(x - __bfloat162float(hi));
}
__device__ __forceinline__ __nv_bfloat162 mk2(__nv_bfloat16 a, __nv_bfloat16 b) {
    __nv_bfloat162 r; r.x = a; r.y = b; return r;
}

// ---------------- K1: embedding -> bf16-split state ------------------------
__global__ void k_embed(const float* __restrict__ nodes,
                        const float* __restrict__ Wemb,
                        const float* __restrict__ bemb,
                        __nv_bfloat16* __restrict__ ahi,
                        __nv_bfloat16* __restrict__ alo) {
    __shared__ float nsh[16][64];
    const int row0 = blockIdx.x * 16;
    const int d = threadIdx.x;
    #pragma unroll
    for (int l = 0; l < 8; l++) {
        int e = threadIdx.x + l * 128;
        nsh[e >> 6][e & 63] = nodes[row0 * 64 + e];
    }
    __syncthreads();
    float acc[16];
    #pragma unroll
    for (int r = 0; r < 16; r++) acc[r] = 0.f;
    for (int k = 0; k < 64; k++) {
        float w = Wemb[k * 128 + d];
        #pragma unroll
        for (int r = 0; r < 16; r++) acc[r] += nsh[r][k] * w;
    }
    float b = bemb[d];
    #pragma unroll
    for (int r = 0; r < 16; r++) {
        float v = acc[r] + b;
        v = v > 0.f ? v : 0.f;
        __nv_bfloat16 h, lo;
        bsplit(v, h, lo);
        ahi[(size_t)(row0 + r) * 128 + d] = h;
        alo[(size_t)(row0 + r) * 128 + d] = lo;
    }
}

// ---------------- split W into bf16 hi/lo ----------------------------------
__global__ void k_split_w(const float* __restrict__ W,
                          __nv_bfloat16* __restrict__ whi,
                          __nv_bfloat16* __restrict__ wlo) {
    int t = blockIdx.x * 256 + threadIdx.x;
    float4 v = *(const float4*)&W[(size_t)t * 4];
    __nv_bfloat16 h0,l0,h1,l1,h2,l2,h3,l3;
    bsplit(v.x,h0,l0); bsplit(v.y,h1,l1); bsplit(v.z,h2,l2); bsplit(v.w,h3,l3);
    *(__nv_bfloat162*)&whi[(size_t)t*4]   = mk2(h0,h1);
    *(__nv_bfloat162*)&whi[(size_t)t*4+2] = mk2(h2,h3);
    *(__nv_bfloat162*)&wlo[(size_t)t*4]   = mk2(l0,l1);
    *(__nv_bfloat162*)&wlo[(size_t)t*4+2] = mk2(l2,l3);
}

// ---------------- K2: V(bf16 split, unnormalized) = A @ W + s1/s2 dots -----
template<int K>
__global__ void k_gemm_wh(const __nv_bfloat16* __restrict__ Ahi,
                          const __nv_bfloat16* __restrict__ Alo,
                          const __nv_bfloat16* __restrict__ Whi,
                          const __nv_bfloat16* __restrict__ Wlo,
                          __nv_bfloat16* __restrict__ vhi,
                          __nv_bfloat16* __restrict__ vlo,
                          const float* __restrict__ a1w,
                          const float* __restrict__ a2w,
                          float* __restrict__ s1,
                          float* __restrict__ s2) {
    const int eh   = blockIdx.y;
    const int row0 = blockIdx.x * 64;
    __shared__ __align__(16) __nv_bfloat16 sAh[2][64][40], sAl[2][64][40];
    __shared__ __align__(16) __nv_bfloat16 sBh[2][32][136], sBl[2][32][136];

    const int L = threadIdx.x, lane = L & 31, w = L >> 5;
    const int mt = w & 3, nh = w >> 2;
    float c[8][4];
    #pragma unroll
    for (int i = 0; i < 8; i++)
        #pragma unroll
        for (int j = 0; j < 4; j++) c[i][j] = 0.f;

    const __nv_bfloat16* Wh_g = Whi + (size_t)eh * K * 128;
    const __nv_bfloat16* Wl_g = Wlo + (size_t)eh * K * 128;

    auto load_tiles = [&](int kt, int buf) {
        int r = L >> 2, c8 = (L & 3) * 8;
        cpa16(&sAh[buf][r][c8], &Ahi[(size_t)(row0 + r) * K + kt + c8]);
        cpa16(&sAl[buf][r][c8], &Alo[(size_t)(row0 + r) * K + kt + c8]);
        #pragma unroll
        for (int l = 0; l < 2; l++) {
            int cc = L + l * 256;
            int br = cc >> 4, d8 = (cc & 15) * 8;
            cpa16(&sBh[buf][br][d8], &Wh_g[(size_t)(kt + br) * 128 + d8]);
            cpa16(&sBl[buf][br][d8], &Wl_g[(size_t)(kt + br) * 128 + d8]);
        }
        CPA_COMMIT;
    };

    const int nk = K / 32;
    load_tiles(0, 0);
    for (int i = 0; i < nk; i++) {
        if (i + 1 < nk) { load_tiles((i + 1) * 32, (i + 1) & 1); CPA_WAIT1; }
        else           { CPA_WAIT0; }
        __syncthreads();
        const int buf = i & 1;

        unsigned ah[2][4], al[2][4];
        {
            int r = lane & 15, co = (lane >> 4) * 8;
            #pragma unroll
            for (int ks = 0; ks < 2; ks++) {
                LDMX4(ah[ks][0],ah[ks][1],ah[ks][2],ah[ks][3],
                      su32(&sAh[buf][mt*16 + r][ks*16 + co]));
                LDMX4(al[ks][0],al[ks][1],al[ks][2],al[ks][3],
                      su32(&sAl[buf][mt*16 + r][ks*16 + co]));
            }
        }
        #pragma unroll
        for (int ks = 0; ks < 2; ks++) {
            #pragma unroll
            for (int pr = 0; pr < 4; pr++) {
                int row = ks*16 + (lane & 15);
                int col = nh*64 + pr*16 + (lane >> 4)*8;
                unsigned bh0,bh1,bh2,bh3, bl0,bl1,bl2,bl3;
                LDMX4T(bh0,bh1,bh2,bh3, su32(&sBh[buf][row][col]));
                LDMX4T(bl0,bl1,bl2,bl3, su32(&sBl[buf][row][col]));
                MMA(c[pr*2],   ah[ks], bh0, bh1);
                MMA(c[pr*2],   ah[ks], bl0, bl1);
                MMA(c[pr*2],   al[ks], bh0, bh1);
                MMA(c[pr*2+1], ah[ks], bh2, bh3);
                MMA(c[pr*2+1], ah[ks], bl2, bl3);
                MMA(c[pr*2+1], al[ks], bh2, bh3);
            }
        }
        __syncthreads();
    }

    // epilogue: bf16-split V write (unnormalized) + s1/s2 partial dots
    __nv_bfloat16* vh = vhi + (size_t)eh * ROWS * 128;
    __nv_bfloat16* vl = vlo + (size_t)eh * ROWS * 128;
    int m = row0 + mt*16 + (lane >> 2);
    float d1a = 0.f, d2a = 0.f, d1b = 0.f, d2b = 0.f;
    #pragma unroll
    for (int nt = 0; nt < 8; nt++) {
        int n = nh*64 + nt*8 + (lane & 3)*2;
        float v0 = c[nt][0], v1 = c[nt][1], v2 = c[nt][2], v3 = c[nt][3];
        __nv_bfloat16 h0,l0,h1,l1,h2,l2,h3,l3;
        bsplit(v0,h0,l0); bsplit(v1,h1,l1); bsplit(v2,h2,l2); bsplit(v3,h3,l3);
        *(__nv_bfloat162*)&vh[(size_t)m     * 128 + n] = mk2(h0,h1);
        *(__nv_bfloat162*)&vl[(size_t)m     * 128 + n] = mk2(l0,l1);
        *(__nv_bfloat162*)&vh[(size_t)(m+8) * 128 + n] = mk2(h2,h3);
        *(__nv_bfloat162*)&vl[(size_t)(m+8) * 128 + n] = mk2(l2,l3);
        float a1x = a1w[eh*128 + n], a1y = a1w[eh*128 + n + 1];
        float a2x = a2w[eh*128 + n], a2y = a2w[eh*128 + n + 1];
        d1a += v0*a1x + v1*a1y;  d2a += v0*a2x + v1*a2y;
        d1b += v2*a1x + v3*a1y;  d2b += v2*a2x + v3*a2y;
    }
    #pragma unroll
    for (int o = 1; o <= 2; o <<= 1) {
        d1a += __shfl_xor_sync(0xffffffffu, d1a, o);
        d2a += __shfl_xor_sync(0xffffffffu, d2a, o);
        d1b += __shfl_xor_sync(0xffffffffu, d1b, o);
        d2b += __shfl_xor_sync(0xffffffffu, d2b, o);
    }
    if ((lane & 3) == 0) {
        atomicAdd(&s1[eh*ROWS + m],     d1a);
        atomicAdd(&s2[eh*ROWS + m],     d2a);
        atomicAdd(&s1[eh*ROWS + m + 8], d1b);
        atomicAdd(&s2[eh*ROWS + m + 8], d2b);
    }
}

// ---------------- K4: softmax column sums (i-chunk 16; bias folded in) -----
__global__ void k_colsum(const float* __restrict__ edges,
                         const float* __restrict__ s1,
                         const float* __restrict__ s2,
                         const float* __restrict__ a1b,
                         const float* __restrict__ a2b,
                         float* __restrict__ cs) {
    const int b  = blockIdx.y;
    const int j  = blockIdx.x * 128 + threadIdx.x;
    const int i0 = blockIdx.z * 16;
    __shared__ float s1sh[4][16];
    if (threadIdx.x < 64) {
        int eh = threadIdx.x >> 4, ii = threadIdx.x & 15;
        s1sh[eh][ii] = s1[eh * ROWS + b * Nq + i0 + ii] + a1b[eh] + a2b[eh];
    }
    __syncthreads();
    float s2r[4], acc[4] = {0.f, 0.f, 0.f, 0.f};
    #pragma unroll
    for (int eh = 0; eh < 4; eh++) s2r[eh] = s2[eh * ROWS + b * Nq + j];

    const float2* ep = (const float2*)edges + (size_t)(b * Nq + i0) * Nq + j;
    for (int ib = 0; ib < 16; ib += 8) {
        float2 ed8[8];
        #pragma unroll
        for (int u = 0; u < 8; u++)
            ed8[u] = ep[(size_t)(ib + u) * Nq];
        #pragma unroll
        for (int u = 0; u < 8; u++) {
            #pragma unroll
            for (int eh = 0; eh < 4; eh++) {
                float z = s1sh[eh][ib + u] + s2r[eh];
                z = z > 0.f ? z : 0.2f * z;
                z += (eh & 2) ? ed8[u].y : ed8[u].x;
                acc[eh] += __expf(z);
            }
        }
    }
    #pragma unroll
    for (int eh = 0; eh < 4; eh++)
        atomicAdd(&cs[eh * ROWS + b * Nq + j], acc[eh]);
}

// ---------------- K4b: cs -> -ln(cs) (in place) ----------------------------
__global__ void k_lncs(float* __restrict__ cs) {
    int t = blockIdx.x * 256 + threadIdx.x;
    cs[t] = -__logf(cs[t]);
}

// ---------------- K5: fused attention aggregation ---------------------------
// P = exp(leaky(s1+s2) + edge + lncs_j)  (normalization inside exponent);
// V is raw Wh in bf16 hi/lo. launch_bounds caps regs at 85 -> 3 blocks/SM.
template<int LAYER>
__global__ void __launch_bounds__(256, 3)
k_msg(const float* __restrict__ edges,
      const float* __restrict__ s1g,
      const float* __restrict__ s2g,
      const float* __restrict__ a1b,
      const float* __restrict__ a2b,
      const float* __restrict__ lncs,
      const __nv_bfloat16* __restrict__ Vhi,
      const __nv_bfloat16* __restrict__ Vlo,
      const float* __restrict__ SB,
      float* __restrict__ out,
      __nv_bfloat16* __restrict__ a1hi,
      __nv_bfloat16* __restrict__ a1lo) {
    const int b  = blockIdx.y;
    const int eh = blockIdx.z;
    const int e  = eh >> 1;
    const int i0 = blockIdx.x * 64;

    __shared__ __align__(16) __nv_bfloat16 Phi[2][64][40], Plo[2][64][40];
    __shared__ __align__(16) __nv_bfloat16 sVh[2][32][136], sVl[2][32][136];
    __shared__ float s1sh[64];

    const int L = threadIdx.x, lane = L & 31, w = L >> 5;
    const int mt = w & 3, nh = w >> 2;
    const int pjj = L & 31, pib = L >> 5;
    float c[8][4];
    #pragma unroll
    for (int i = 0; i < 8; i++)
        #pragma unroll
        for (int j = 0; j < 4; j++) c[i][j] = 0.f;

    if (L < 64)
        s1sh[L] = s1g[eh * ROWS + b * Nq + i0 + L] + a1b[eh] + a2b[eh];

    const __nv_bfloat16* Vh_g = Vhi + ((size_t)eh * ROWS + b * Nq) * 128;
    const __nv_bfloat16* Vl_g = Vlo + ((size_t)eh * ROWS + b * Nq) * 128;
    const float* s2base = s2g + eh * ROWS + b * Nq;
    const float* lnbase = lncs + eh * ROWS + b * Nq;
    const float* ebase0 =
        edges + (((size_t)(b * Nq + i0 + pib) * Nq)) * 2 + e;

    auto load_v = [&](int j0, int buf) {
        #pragma unroll
        for (int l = 0; l < 2; l++) {
            int cc = L + l * 256;
            int jj = cc >> 4, d8 = (cc & 15) * 8;
            cpa16(&sVh[buf][jj][d8], &Vh_g[(size_t)(j0 + jj) * 128 + d8]);
            cpa16(&sVl[buf][jj][d8], &Vl_g[(size_t)(j0 + jj) * 128 + d8]);
        }
        CPA_COMMIT;
    };

    auto store_p = [&](int pb, float s2v, float lnv, const float* ed) {
        #pragma unroll
        for (int rr = 0; rr < 8; rr++) {
            int i = pib + rr * 8;
            float z = s1sh[i] + s2v;
            z = z > 0.f ? z : 0.2f * z;
            float p = __expf(z + ed[rr] + lnv);
            __nv_bfloat16 h, lo;
            bsplit(p, h, lo);
            Phi[pb][i][pjj] = h;
            Plo[pb][i][pjj] = lo;
        }
    };

    load_v(0, 0);
    {
        __syncthreads();
        float ed[8];
        const float* eb = ebase0 + (size_t)pjj * 2;
        #pragma unroll
        for (int rr = 0; rr < 8; rr++)
            ed[rr] = eb[(size_t)rr * 8 * Nq * 2];
        store_p(0, s2base[pjj], lnbase[pjj], ed);
    }

    for (int ci = 0; ci < Nq / 32; ci++) {
        const int buf = ci & 1;
        float edn[8], s2n = 0.f, lnn = 0.f;
        const bool has_next = (ci + 1 < Nq / 32);
        if (has_next) {
            int j0n = (ci + 1) * 32;
            s2n = s2base[j0n + pjj];
            lnn = lnbase[j0n + pjj];
            const float* eb = ebase0 + (size_t)(j0n + pjj) * 2;
            #pragma unroll
            for (int rr = 0; rr < 8; rr++)
                edn[rr] = eb[(size_t)rr * 8 * Nq * 2];
            load_v(j0n, (ci + 1) & 1);
            CPA_WAIT1;
        } else {
            CPA_WAIT0;
        }
        __syncthreads();

        unsigned ah[2][4], al[2][4];
        {
            int r = lane & 15, co = (lane >> 4) * 8;
            #pragma unroll
            for (int ks = 0; ks < 2; ks++) {
                LDMX4(ah[ks][0],ah[ks][1],ah[ks][2],ah[ks][3],
                      su32(&Phi[buf][mt*16 + r][ks*16 + co]));
                LDMX4(al[ks][0],al[ks][1],al[ks][2],al[ks][3],
                      su32(&Plo[buf][mt*16 + r][ks*16 + co]));
            }
        }
        #pragma unroll
        for (int ks = 0; ks < 2; ks++) {
            #pragma unroll
            for (int pr = 0; pr < 4; pr++) {
                int row = ks*16 + (lane & 15);
                int col = nh*64 + pr*16 + (lane >> 4)*8;
                unsigned bh0,bh1,bh2,bh3, bl0,bl1,bl2,bl3;
                LDMX4T(bh0,bh1,bh2,bh3, su32(&sVh[buf][row][col]));
                LDMX4T(bl0,bl1,bl2,bl3, su32(&sVl[buf][row][col]));
                MMA(c[pr*2],   ah[ks], bh0, bh1);
                MMA(c[pr*2],   ah[ks], bl0, bl1);
                MMA(c[pr*2],   al[ks], bh0, bh1);
                MMA(c[pr*2+1], ah[ks], bh2, bh3);
                MMA(c[pr*2+1], ah[ks], bl2, bl3);
                MMA(c[pr*2+1], al[ks], bh2, bh3);
            }
        }
        if (has_next) store_p(buf ^ 1, s2n, lnn, edn);
        __syncthreads();
    }

    int m = i0 + mt*16 + (lane >> 2);
    #pragma unroll
    for (int nt = 0; nt < 8; nt++) {
        int n = nh*64 + nt*8 + (lane & 3)*2;
        float sb0 = SB[eh*128 + n], sb1 = SB[eh*128 + n + 1];
        float v0 = c[nt][0] + sb0, v1 = c[nt][1] + sb1;
        float v2 = c[nt][2] + sb0, v3 = c[nt][3] + sb1;
        if (LAYER == 0) {
            __nv_bfloat16 h0,l0,h1,l1,h2,l2,h3,l3;
            bsplit(v0,h0,l0); bsplit(v1,h1,l1);
            bsplit(v2,h2,l2); bsplit(v3,h3,l3);
            size_t r0 = (size_t)(b*Nq + m)   * IN1q + eh*128 + n;
            size_t r1 = (size_t)(b*Nq + m+8) * IN1q + eh*128 + n;
            *(__nv_bfloat162*)&a1hi[r0] = mk2(h0,h1);
            *(__nv_bfloat162*)&a1lo[r0] = mk2(l0,l1);
            *(__nv_bfloat162*)&a1hi[r1] = mk2(h2,h3);
            *(__nv_bfloat162*)&a1lo[r1] = mk2(l2,l3);
        } else {
            v0 = v0 > 0.f ? v0 : expm1f(v0);
            v1 = v1 > 0.f ? v1 : expm1f(v1);
            v2 = v2 > 0.f ? v2 : expm1f(v2);
            v3 = v3 > 0.f ? v3 : expm1f(v3);
            atomicAdd(&out[(size_t)(b*Nq + m)   * 128 + n],     0.25f * v0);
            atomicAdd(&out[(size_t)(b*Nq + m)   * 128 + n + 1], 0.25f * v1);
            atomicAdd(&out[(size_t)(b*Nq + m+8) * 128 + n],     0.25f * v2);
            atomicAdd(&out[(size_t)(b*Nq + m+8) * 128 + n + 1], 0.25f * v3);
        }
    }
}

// ---------------- K6: final projection -------------------------------------
__global__ void k_out(const float* __restrict__ S,
                      const float* __restrict__ Wout,
                      const float* __restrict__ bout,
                      float* __restrict__ out) {
    __shared__ float Ssh[32][128];
    const int row0 = blockIdx.x * 32;
    #pragma unroll
    for (int l = 0; l < 16; l++) {
        int ee = threadIdx.x + l * 256;
        int r = ee >> 7, k = ee & 127;
        Ssh[r][k] = S[(size_t)(row0 + r) * 128 + k];
    }
    __syncthreads();
    const int c  = threadIdx.x & 63;
    const int ty = threadIdx.x >> 6;
    float acc[8];
    #pragma unroll
    for (int r = 0; r < 8; r++) acc[r] = 0.f;
    for (int k = 0; k < 128; k++) {
        float w = Wout[k * 64 + c];
        #pragma unroll
        for (int r = 0; r < 8; r++) acc[r] += Ssh[ty * 8 + r][k] * w;
    }
    float bb = bout[c];
    #pragma unroll
    for (int r = 0; r < 8; r++)
        out[(size_t)(row0 + ty * 8 + r) * 64 + c] = acc[r] + bb;
}

// ---------------- host launcher --------------------------------------------
extern "C" void kernel_launch(void* const* d_in, const int* in_sizes, int n_in,
                              void* d_out, int out_size) {
    const float* nodes = (const float*)d_in[0];
    const float* edges = (const float*)d_in[1];
    const float* Wemb  = (const float*)d_in[2];
    const float* bemb  = (const float*)d_in[3];
    const float* W0    = (const float*)d_in[4];
    const float* A1w0  = (const float*)d_in[5];
    const float* A1b0  = (const float*)d_in[6];
    const float* A2w0  = (const float*)d_in[7];
    const float* A2b0  = (const float*)d_in[8];
    const float* SB0   = (const float*)d_in[9];
    const float* W1    = (const float*)d_in[10];
    const float* A1w1  = (const float*)d_in[11];
    const float* A1b1  = (const float*)d_in[12];
    const float* A2w1  = (const float*)d_in[13];
    const float* A2b1  = (const float*)d_in[14];
    const float* SB1   = (const float*)d_in[15];
    const float* Wout  = (const float*)d_in[16];
    const float* bout  = (const float*)d_in[17];

    float *s1, *s2, *cs, *state2;
    __nv_bfloat16 *a0hi, *a0lo, *a1hi, *a1lo, *wshi, *wslo, *vhi, *vlo;
    cudaGetSymbolAddress((void**)&s1,     g_s1);
    cudaGetSymbolAddress((void**)&s2,     g_s2);
    cudaGetSymbolAddress((void**)&cs,     g_cs);
    cudaGetSymbolAddress((void**)&state2, g_state2);
    cudaGetSymbolAddress((void**)&a0hi,   g_A0hi);
    cudaGetSymbolAddress((void**)&a0lo,   g_A0lo);
    cudaGetSymbolAddress((void**)&a1hi,   g_A1hi);
    cudaGetSymbolAddress((void**)&a1lo,   g_A1lo);
    cudaGetSymbolAddress((void**)&wshi,   g_Wshi);
    cudaGetSymbolAddress((void**)&wslo,   g_Wslo);
    cudaGetSymbolAddress((void**)&vhi,    g_Vhi);
    cudaGetSymbolAddress((void**)&vlo,    g_Vlo);

    const size_t SBYTES = (size_t)EHq * ROWS * sizeof(float);
    cudaMemsetAsync(state2, 0, (size_t)ROWS * Dq * sizeof(float));

    k_embed<<<ROWS / 16, 128>>>(nodes, Wemb, bemb, a0hi, a0lo);

    // ---- layer 0 ----
    k_split_w<<<(EHq * 128 * 128 / 4) / 256, 256>>>(W0, wshi, wslo);
    cudaMemsetAsync(s1, 0, SBYTES);
    cudaMemsetAsync(s2, 0, SBYTES);
    cudaMemsetAsync(cs, 0, SBYTES);
    k_gemm_wh<128><<<dim3(ROWS / 64, EHq), 256>>>(a0hi, a0lo, wshi, wslo,
                                                  vhi, vlo, A1w0, A2w0, s1, s2);
    k_colsum<<<dim3(Nq / 128, Bq, 64), 128>>>(edges, s1, s2, A1b0, A2b0, cs);
    k_lncs<<<(EHq * ROWS) / 256, 256>>>(cs);
    k_msg<0><<<dim3(Nq / 64, Bq, EHq), 256>>>(edges, s1, s2, A1b0, A2b0, cs,
                                              vhi, vlo, SB0,
                                              nullptr, a1hi, a1lo);

    // ---- layer 1 ----
    k_split_w<<<(EHq * 512 * 128 / 4) / 256, 256>>>(W1, wshi, wslo);
    cudaMemsetAsync(s1, 0, SBYTES);
    cudaMemsetAsync(s2, 0, SBYTES);
    cudaMemsetAsync(cs, 0, SBYTES);
    k_gemm_wh<512><<<dim3(ROWS / 64, EHq), 256>>>(a1hi, a1lo, wshi, wslo,
                                                  vhi, vlo, A1w1, A2w1, s1, s2);
    k_colsum<<<dim3(Nq / 128, Bq, 64), 128>>>(edges, s1, s2, A1b1, A2b1, cs);
    k_lncs<<<(EHq * ROWS) / 256, 256>>>(cs);
    k_msg<1><<<dim3(Nq / 64, Bq, EHq), 256>>>(edges, s1, s2, A1b1, A2b1, cs,
                                              vhi, vlo, SB1,
                                              state2, nullptr, nullptr);

    k_out<<<ROWS / 32, 256>>>(state2, Wout, bout, (float*)d_out);
}

// round 17
// speedup vs baseline: 1.0137x; 1.0137x over previous
#include <cuda_runtime.h>
#include <cuda_bf16.h>
#include <math.h>

// Problem constants
#define Bq   8
#define Nq   1024
#define Iq   64
#define Eq   2
#define Hq   2
#define Dq   128
#define Oq   64
#define EHq  4
#define ROWS (Bq*Nq)        // 8192
#define IN1q (Eq*Hq*Dq)     // 512
#define LOG2E 1.4426950408889634f

// ---------------- scratch (device globals; no cudaMalloc allowed) ----------
__device__ float g_s1    [EHq*ROWS];      // prescaled by LOG2E
__device__ float g_s2    [EHq*ROWS];      // prescaled by LOG2E
__device__ float g_cs    [EHq*ROWS];      // colsum, then -log2(colsum)
__device__ float g_state2[ROWS*Dq];
__device__ __nv_bfloat16 g_A0hi[ROWS*Dq],   g_A0lo[ROWS*Dq];
__device__ __nv_bfloat16 g_A1hi[ROWS*IN1q], g_A1lo[ROWS*IN1q];
__device__ __nv_bfloat16 g_Wshi[EHq*IN1q*Dq], g_Wslo[EHq*IN1q*Dq];
__device__ __nv_bfloat16 g_Vhi [EHq*ROWS*Dq], g_Vlo [EHq*ROWS*Dq];

// ---------------- helpers ---------------------------------------------------
__device__ __forceinline__ unsigned su32(const void* p) {
    return (unsigned)__cvta_generic_to_shared(p);
}
__device__ __forceinline__ float ex2f(float x) {
    float r; asm("ex2.approx.f32 %0, %1;" : "=f"(r) : "f"(x)); return r;
}
__device__ __forceinline__ void cpa16(void* dst, const void* src) {
    asm volatile("cp.async.cg.shared.global [%0], [%1], 16;"
                 :: "r"(su32(dst)), "l"(src));
}
#define CPA_COMMIT asm volatile("cp.async.commit_group;")
#define CPA_WAIT1  asm volatile("cp.async.wait_group 1;")
#define CPA_WAIT0  asm volatile("cp.async.wait_group 0;")

#define LDMX4(r0,r1,r2,r3,addr) \
    asm volatile("ldmatrix.sync.aligned.m8n8.x4.shared.b16 {%0,%1,%2,%3}, [%4];" \
        : "=r"(r0),"=r"(r1),"=r"(r2),"=r"(r3) : "r"(addr))
#define LDMX4T(r0,r1,r2,r3,addr) \
    asm volatile("ldmatrix.sync.aligned.m8n8.x4.trans.shared.b16 {%0,%1,%2,%3}, [%4];" \
        : "=r"(r0),"=r"(r1),"=r"(r2),"=r"(r3) : "r"(addr))
#define MMA(c,a,b0,b1) \
    asm volatile("mma.sync.aligned.m16n8k16.row.col.f32.bf16.bf16.f32 " \
        "{%0,%1,%2,%3}, {%4,%5,%6,%7}, {%8,%9}, {%0,%1,%2,%3};" \
        : "+f"((c)[0]),"+f"((c)[1]),"+f"((c)[2]),"+f"((c)[3]) \
        : "r"((a)[0]),"r"((a)[1]),"r"((a)[2]),"r"((a)[3]), "r"(b0),"r"(b1))

__device__ __forceinline__ void bsplit(float x, __nv_bfloat16& hi, __nv_bfloat16& lo) {
    hi = __float2bfloat16(x);
    lo = __float2bfloat16(x - __bfloat162float(hi));
}
__device__ __forceinline__ __nv_bfloat162 mk2(__nv_bfloat16 a, __nv_bfloat16 b) {
    __nv_bfloat162 r; r.x = a; r.y = b; return r;
}

// ---------------- K1: embedding -> bf16-split state ------------------------
__global__ void k_embed(const float* __restrict__ nodes,
                        const float* __restrict__ Wemb,
                        const float* __restrict__ bemb,
                        __nv_bfloat16* __restrict__ ahi,
                        __nv_bfloat16* __restrict__ alo) {
    __shared__ float nsh[16][64];
    const int row0 = blockIdx.x * 16;
    const int d = threadIdx.x;
    #pragma unroll
    for (int l = 0; l < 8; l++) {
        int e = threadIdx.x + l * 128;
        nsh[e >> 6][e & 63] = nodes[row0 * 64 + e];
    }
    __syncthreads();
    float acc[16];
    #pragma unroll
    for (int r = 0; r < 16; r++) acc[r] = 0.f;
    for (int k = 0; k < 64; k++) {
        float w = Wemb[k * 128 + d];
        #pragma unroll
        for (int r = 0; r < 16; r++) acc[r] += nsh[r][k] * w;
    }
    float b = bemb[d];
    #pragma unroll
    for (int r = 0; r < 16; r++) {
        float v = acc[r] + b;
        v = v > 0.f ? v : 0.f;
        __nv_bfloat16 h, lo;
        bsplit(v, h, lo);
        ahi[(size_t)(row0 + r) * 128 + d] = h;
        alo[(size_t)(row0 + r) * 128 + d] = lo;
    }
}

// ---------------- split W into bf16 hi/lo ----------------------------------
__global__ void k_split_w(const float* __restrict__ W,
                          __nv_bfloat16* __restrict__ whi,
                          __nv_bfloat16* __restrict__ wlo) {
    int t = blockIdx.x * 256 + threadIdx.x;
    float4 v = *(const float4*)&W[(size_t)t * 4];
    __nv_bfloat16 h0,l0,h1,l1,h2,l2,h3,l3;
    bsplit(v.x,h0,l0); bsplit(v.y,h1,l1); bsplit(v.z,h2,l2); bsplit(v.w,h3,l3);
    *(__nv_bfloat162*)&whi[(size_t)t*4]   = mk2(h0,h1);
    *(__nv_bfloat162*)&whi[(size_t)t*4+2] = mk2(h2,h3);
    *(__nv_bfloat162*)&wlo[(size_t)t*4]   = mk2(l0,l1);
    *(__nv_bfloat162*)&wlo[(size_t)t*4+2] = mk2(l2,l3);
}

// ---------------- K2: V(bf16 split, unnormalized) = A @ W + s1/s2 dots -----
// s1/s2 written prescaled by LOG2E (exp2 re-parameterization downstream).
template<int K>
__global__ void k_gemm_wh(const __nv_bfloat16* __restrict__ Ahi,
                          const __nv_bfloat16* __restrict__ Alo,
                          const __nv_bfloat16* __restrict__ Whi,
                          const __nv_bfloat16* __restrict__ Wlo,
                          __nv_bfloat16* __restrict__ vhi,
                          __nv_bfloat16* __restrict__ vlo,
                          const float* __restrict__ a1w,
                          const float* __restrict__ a2w,
                          float* __restrict__ s1,
                          float* __restrict__ s2) {
    const int eh   = blockIdx.y;
    const int row0 = blockIdx.x * 64;
    __shared__ __align__(16) __nv_bfloat16 sAh[2][64][40], sAl[2][64][40];
    __shared__ __align__(16) __nv_bfloat16 sBh[2][32][136], sBl[2][32][136];

    const int L = threadIdx.x, lane = L & 31, w = L >> 5;
    const int mt = w & 3, nh = w >> 2;
    float c[8][4];
    #pragma unroll
    for (int i = 0; i < 8; i++)
        #pragma unroll
        for (int j = 0; j < 4; j++) c[i][j] = 0.f;

    const __nv_bfloat16* Wh_g = Whi + (size_t)eh * K * 128;
    const __nv_bfloat16* Wl_g = Wlo + (size_t)eh * K * 128;

    auto load_tiles = [&](int kt, int buf) {
        int r = L >> 2, c8 = (L & 3) * 8;
        cpa16(&sAh[buf][r][c8], &Ahi[(size_t)(row0 + r) * K + kt + c8]);
        cpa16(&sAl[buf][r][c8], &Alo[(size_t)(row0 + r) * K + kt + c8]);
        #pragma unroll
        for (int l = 0; l < 2; l++) {
            int cc = L + l * 256;
            int br = cc >> 4, d8 = (cc & 15) * 8;
            cpa16(&sBh[buf][br][d8], &Wh_g[(size_t)(kt + br) * 128 + d8]);
            cpa16(&sBl[buf][br][d8], &Wl_g[(size_t)(kt + br) * 128 + d8]);
        }
        CPA_COMMIT;
    };

    const int nk = K / 32;
    load_tiles(0, 0);
    for (int i = 0; i < nk; i++) {
        if (i + 1 < nk) { load_tiles((i + 1) * 32, (i + 1) & 1); CPA_WAIT1; }
        else           { CPA_WAIT0; }
        __syncthreads();
        const int buf = i & 1;

        unsigned ah[2][4], al[2][4];
        {
            int r = lane & 15, co = (lane >> 4) * 8;
            #pragma unroll
            for (int ks = 0; ks < 2; ks++) {
                LDMX4(ah[ks][0],ah[ks][1],ah[ks][2],ah[ks][3],
                      su32(&sAh[buf][mt*16 + r][ks*16 + co]));
                LDMX4(al[ks][0],al[ks][1],al[ks][2],al[ks][3],
                      su32(&sAl[buf][mt*16 + r][ks*16 + co]));
            }
        }
        #pragma unroll
        for (int ks = 0; ks < 2; ks++) {
            #pragma unroll
            for (int pr = 0; pr < 4; pr++) {
                int row = ks*16 + (lane & 15);
                int col = nh*64 + pr*16 + (lane >> 4)*8;
                unsigned bh0,bh1,bh2,bh3, bl0,bl1,bl2,bl3;
                LDMX4T(bh0,bh1,bh2,bh3, su32(&sBh[buf][row][col]));
                LDMX4T(bl0,bl1,bl2,bl3, su32(&sBl[buf][row][col]));
                MMA(c[pr*2],   ah[ks], bh0, bh1);
                MMA(c[pr*2],   ah[ks], bl0, bl1);
                MMA(c[pr*2],   al[ks], bh0, bh1);
                MMA(c[pr*2+1], ah[ks], bh2, bh3);
                MMA(c[pr*2+1], ah[ks], bl2, bl3);
                MMA(c[pr*2+1], al[ks], bh2, bh3);
            }
        }
        __syncthreads();
    }

    // epilogue: bf16-split V write (unnormalized) + s1/s2 partial dots
    __nv_bfloat16* vh = vhi + (size_t)eh * ROWS * 128;
    __nv_bfloat16* vl = vlo + (size_t)eh * ROWS * 128;
    int m = row0 + mt*16 + (lane >> 2);
    float d1a = 0.f, d2a = 0.f, d1b = 0.f, d2b = 0.f;
    #pragma unroll
    for (int nt = 0; nt < 8; nt++) {
        int n = nh*64 + nt*8 + (lane & 3)*2;
        float v0 = c[nt][0], v1 = c[nt][1], v2 = c[nt][2], v3 = c[nt][3];
        __nv_bfloat16 h0,l0,h1,l1,h2,l2,h3,l3;
        bsplit(v0,h0,l0); bsplit(v1,h1,l1); bsplit(v2,h2,l2); bsplit(v3,h3,l3);
        *(__nv_bfloat162*)&vh[(size_t)m     * 128 + n] = mk2(h0,h1);
        *(__nv_bfloat162*)&vl[(size_t)m     * 128 + n] = mk2(l0,l1);
        *(__nv_bfloat162*)&vh[(size_t)(m+8) * 128 + n] = mk2(h2,h3);
        *(__nv_bfloat162*)&vl[(size_t)(m+8) * 128 + n] = mk2(l2,l3);
        float a1x = a1w[eh*128 + n], a1y = a1w[eh*128 + n + 1];
        float a2x = a2w[eh*128 + n], a2y = a2w[eh*128 + n + 1];
        d1a += v0*a1x + v1*a1y;  d2a += v0*a2x + v1*a2y;
        d1b += v2*a1x + v3*a1y;  d2b += v2*a2x + v3*a2y;
    }
    #pragma unroll
    for (int o = 1; o <= 2; o <<= 1) {
        d1a += __shfl_xor_sync(0xffffffffu, d1a, o);
        d2a += __shfl_xor_sync(0xffffffffu, d2a, o);
        d1b += __shfl_xor_sync(0xffffffffu, d1b, o);
        d2b += __shfl_xor_sync(0xffffffffu, d2b, o);
    }
    if ((lane & 3) == 0) {
        atomicAdd(&s1[eh*ROWS + m],     d1a * LOG2E);
        atomicAdd(&s2[eh*ROWS + m],     d2a * LOG2E);
        atomicAdd(&s1[eh*ROWS + m + 8], d1b * LOG2E);
        atomicAdd(&s2[eh*ROWS + m + 8], d2b * LOG2E);
    }
}

// ---------------- K4: softmax column sums (exp2 path; bias folded in) ------
__global__ void k_colsum(const float* __restrict__ edges,
                         const float* __restrict__ s1,
                         const float* __restrict__ s2,
                         const float* __restrict__ a1b,
                         const float* __restrict__ a2b,
                         float* __restrict__ cs) {
    const int b  = blockIdx.y;
    const int j  = blockIdx.x * 128 + threadIdx.x;
    const int i0 = blockIdx.z * 32;
    __shared__ float s1sh[4][32];
    if (threadIdx.x < 128) {
        int eh = threadIdx.x >> 5, ii = threadIdx.x & 31;
        s1sh[eh][ii] = s1[eh * ROWS + b * Nq + i0 + ii]
                     + (a1b[eh] + a2b[eh]) * LOG2E;
    }
    __syncthreads();
    float s2r[4], acc[4] = {0.f, 0.f, 0.f, 0.f};
    #pragma unroll
    for (int eh = 0; eh < 4; eh++) s2r[eh] = s2[eh * ROWS + b * Nq + j];

    const float2* ep = (const float2*)edges + (size_t)(b * Nq + i0) * Nq + j;
    for (int ib = 0; ib < 32; ib += 8) {
        float2 ed8[8];
        #pragma unroll
        for (int u = 0; u < 8; u++)
            ed8[u] = ep[(size_t)(ib + u) * Nq];
        #pragma unroll
        for (int u = 0; u < 8; u++) {
            #pragma unroll
            for (int eh = 0; eh < 4; eh++) {
                float z = s1sh[eh][ib + u] + s2r[eh];
                float zl = fmaxf(z, 0.2f * z);             // leaky (scaled)
                float ed = (eh & 2) ? ed8[u].y : ed8[u].x;
                acc[eh] += ex2f(fmaf(ed, LOG2E, zl));
            }
        }
    }
    #pragma unroll
    for (int eh = 0; eh < 4; eh++)
        atomicAdd(&cs[eh * ROWS + b * Nq + j], acc[eh]);
}

// ---------------- K4b: cs -> -log2(cs) (in place) --------------------------
__global__ void k_lncs(float* __restrict__ cs) {
    int t = blockIdx.x * 256 + threadIdx.x;
    cs[t] = -__log2f(cs[t]);
}

// ---------------- K5: fused attention aggregation (exp2 path) ---------------
// P = 2^(leaky(s1'+s2') + ed*LOG2E + log2cs_j); V is raw Wh in bf16 hi/lo.
template<int LAYER>
__global__ void k_msg(const float* __restrict__ edges,
                      const float* __restrict__ s1g,
                      const float* __restrict__ s2g,
                      const float* __restrict__ a1b,
                      const float* __restrict__ a2b,
                      const float* __restrict__ lncs,
                      const __nv_bfloat16* __restrict__ Vhi,
                      const __nv_bfloat16* __restrict__ Vlo,
                      const float* __restrict__ SB,
                      float* __restrict__ out,
                      __nv_bfloat16* __restrict__ a1hi,
                      __nv_bfloat16* __restrict__ a1lo) {
    const int b  = blockIdx.y;
    const int eh = blockIdx.z;
    const int e  = eh >> 1;
    const int i0 = blockIdx.x * 64;

    __shared__ __align__(16) __nv_bfloat16 Phi[2][64][40], Plo[2][64][40];
    __shared__ __align__(16) __nv_bfloat16 sVh[2][32][136], sVl[2][32][136];
    __shared__ float s1sh[64];

    const int L = threadIdx.x, lane = L & 31, w = L >> 5;
    const int mt = w & 3, nh = w >> 2;
    const int pjj = L & 31, pib = L >> 5;
    float c[8][4];
    #pragma unroll
    for (int i = 0; i < 8; i++)
        #pragma unroll
        for (int j = 0; j < 4; j++) c[i][j] = 0.f;

    if (L < 64)
        s1sh[L] = s1g[eh * ROWS + b * Nq + i0 + L]
                + (a1b[eh] + a2b[eh]) * LOG2E;

    const __nv_bfloat16* Vh_g = Vhi + ((size_t)eh * ROWS + b * Nq) * 128;
    const __nv_bfloat16* Vl_g = Vlo + ((size_t)eh * ROWS + b * Nq) * 128;
    const float* s2base = s2g + eh * ROWS + b * Nq;
    const float* lnbase = lncs + eh * ROWS + b * Nq;
    const float* ebase0 =
        edges + (((size_t)(b * Nq + i0 + pib) * Nq)) * 2 + e;

    auto load_v = [&](int j0, int buf) {
        #pragma unroll
        for (int l = 0; l < 2; l++) {
            int cc = L + l * 256;
            int jj = cc >> 4, d8 = (cc & 15) * 8;
            cpa16(&sVh[buf][jj][d8], &Vh_g[(size_t)(j0 + jj) * 128 + d8]);
            cpa16(&sVl[buf][jj][d8], &Vl_g[(size_t)(j0 + jj) * 128 + d8]);
        }
        CPA_COMMIT;
    };

    auto store_p = [&](int pb, float s2v, float lnv, const float* ed) {
        #pragma unroll
        for (int rr = 0; rr < 8; rr++) {
            int i = pib + rr * 8;
            float z = s1sh[i] + s2v;
            float zl = fmaxf(z, 0.2f * z) + lnv;
            float p = ex2f(fmaf(ed[rr], LOG2E, zl));
            __nv_bfloat16 h, lo;
            bsplit(p, h, lo);
            Phi[pb][i][pjj] = h;
            Plo[pb][i][pjj] = lo;
        }
    };

    load_v(0, 0);
    {
        __syncthreads();
        float ed[8];
        const float* eb = ebase0 + (size_t)pjj * 2;
        #pragma unroll
        for (int rr = 0; rr < 8; rr++)
            ed[rr] = eb[(size_t)rr * 8 * Nq * 2];
        store_p(0, s2base[pjj], lnbase[pjj], ed);
    }

    for (int ci = 0; ci < Nq / 32; ci++) {
        const int buf = ci & 1;
        float edn[8], s2n = 0.f, lnn = 0.f;
        const bool has_next = (ci + 1 < Nq / 32);
        if (has_next) {
            int j0n = (ci + 1) * 32;
            s2n = s2base[j0n + pjj];
            lnn = lnbase[j0n + pjj];
            const float* eb = ebase0 + (size_t)(j0n + pjj) * 2;
            #pragma unroll
            for (int rr = 0; rr < 8; rr++)
                edn[rr] = eb[(size_t)rr * 8 * Nq * 2];
            load_v(j0n, (ci + 1) & 1);
            CPA_WAIT1;
        } else {
            CPA_WAIT0;
        }
        __syncthreads();

        unsigned ah[2][4], al[2][4];
        {
            int r = lane & 15, co = (lane >> 4) * 8;
            #pragma unroll
            for (int ks = 0; ks < 2; ks++) {
                LDMX4(ah[ks][0],ah[ks][1],ah[ks][2],ah[ks][3],
                      su32(&Phi[buf][mt*16 + r][ks*16 + co]));
                LDMX4(al[ks][0],al[ks][1],al[ks][2],al[ks][3],
                      su32(&Plo[buf][mt*16 + r][ks*16 + co]));
            }
        }
        #pragma unroll
        for (int ks = 0; ks < 2; ks++) {
            #pragma unroll
            for (int pr = 0; pr < 4; pr++) {
                int row = ks*16 + (lane & 15);
                int col = nh*64 + pr*16 + (lane >> 4)*8;
                unsigned bh0,bh1,bh2,bh3, bl0,bl1,bl2,bl3;
                LDMX4T(bh0,bh1,bh2,bh3, su32(&sVh[buf][row][col]));
                LDMX4T(bl0,bl1,bl2,bl3, su32(&sVl[buf][row][col]));
                MMA(c[pr*2],   ah[ks], bh0, bh1);
                MMA(c[pr*2],   ah[ks], bl0, bl1);
                MMA(c[pr*2],   al[ks], bh0, bh1);
                MMA(c[pr*2+1], ah[ks], bh2, bh3);
                MMA(c[pr*2+1], ah[ks], bl2, bl3);
                MMA(c[pr*2+1], al[ks], bh2, bh3);
            }
        }
        if (has_next) store_p(buf ^ 1, s2n, lnn, edn);
        __syncthreads();
    }

    int m = i0 + mt*16 + (lane >> 2);
    #pragma unroll
    for (int nt = 0; nt < 8; nt++) {
        int n = nh*64 + nt*8 + (lane & 3)*2;
        float sb0 = SB[eh*128 + n], sb1 = SB[eh*128 + n + 1];
        float v0 = c[nt][0] + sb0, v1 = c[nt][1] + sb1;
        float v2 = c[nt][2] + sb0, v3 = c[nt][3] + sb1;
        if (LAYER == 0) {
            __nv_bfloat16 h0,l0,h1,l1,h2,l2,h3,l3;
            bsplit(v0,h0,l0); bsplit(v1,h1,l1);
            bsplit(v2,h2,l2); bsplit(v3,h3,l3);
            size_t r0 = (size_t)(b*Nq + m)   * IN1q + eh*128 + n;
            size_t r1 = (size_t)(b*Nq + m+8) * IN1q + eh*128 + n;
            *(__nv_bfloat162*)&a1hi[r0] = mk2(h0,h1);
            *(__nv_bfloat162*)&a1lo[r0] = mk2(l0,l1);
            *(__nv_bfloat162*)&a1hi[r1] = mk2(h2,h3);
            *(__nv_bfloat162*)&a1lo[r1] = mk2(l2,l3);
        } else {
            v0 = v0 > 0.f ? v0 : expm1f(v0);
            v1 = v1 > 0.f ? v1 : expm1f(v1);
            v2 = v2 > 0.f ? v2 : expm1f(v2);
            v3 = v3 > 0.f ? v3 : expm1f(v3);
            atomicAdd(&out[(size_t)(b*Nq + m)   * 128 + n],     0.25f * v0);
            atomicAdd(&out[(size_t)(b*Nq + m)   * 128 + n + 1], 0.25f * v1);
            atomicAdd(&out[(size_t)(b*Nq + m+8) * 128 + n],     0.25f * v2);
            atomicAdd(&out[(size_t)(b*Nq + m+8) * 128 + n + 1], 0.25f * v3);
        }
    }
}

// ---------------- K6: final projection -------------------------------------
__global__ void k_out(const float* __restrict__ S,
                      const float* __restrict__ Wout,
                      const float* __restrict__ bout,
                      float* __restrict__ out) {
    __shared__ float Ssh[32][128];
    const int row0 = blockIdx.x * 32;
    #pragma unroll
    for (int l = 0; l < 16; l++) {
        int ee = threadIdx.x + l * 256;
        int r = ee >> 7, k = ee & 127;
        Ssh[r][k] = S[(size_t)(row0 + r) * 128 + k];
    }
    __syncthreads();
    const int c  = threadIdx.x & 63;
    const int ty = threadIdx.x >> 6;
    float acc[8];
    #pragma unroll
    for (int r = 0; r < 8; r++) acc[r] = 0.f;
    for (int k = 0; k < 128; k++) {
        float w = Wout[k * 64 + c];
        #pragma unroll
        for (int r = 0; r < 8; r++) acc[r] += Ssh[ty * 8 + r][k] * w;
    }
    float bb = bout[c];
    #pragma unroll
    for (int r = 0; r < 8; r++)
        out[(size_t)(row0 + ty * 8 + r) * 64 + c] = acc[r] + bb;
}

// ---------------- host launcher --------------------------------------------
extern "C" void kernel_launch(void* const* d_in, const int* in_sizes, int n_in,
                              void* d_out, int out_size) {
    const float* nodes = (const float*)d_in[0];
    const float* edges = (const float*)d_in[1];
    const float* Wemb  = (const float*)d_in[2];
    const float* bemb  = (const float*)d_in[3];
    const float* W0    = (const float*)d_in[4];
    const float* A1w0  = (const float*)d_in[5];
    const float* A1b0  = (const float*)d_in[6];
    const float* A2w0  = (const float*)d_in[7];
    const float* A2b0  = (const float*)d_in[8];
    const float* SB0   = (const float*)d_in[9];
    const float* W1    = (const float*)d_in[10];
    const float* A1w1  = (const float*)d_in[11];
    const float* A1b1  = (const float*)d_in[12];
    const float* A2w1  = (const float*)d_in[13];
    const float* A2b1  = (const float*)d_in[14];
    const float* SB1   = (const float*)d_in[15];
    const float* Wout  = (const float*)d_in[16];
    const float* bout  = (const float*)d_in[17];

    float *s1, *s2, *cs, *state2;
    __nv_bfloat16 *a0hi, *a0lo, *a1hi, *a1lo, *wshi, *wslo, *vhi, *vlo;
    cudaGetSymbolAddress((void**)&s1,     g_s1);
    cudaGetSymbolAddress((void**)&s2,     g_s2);
    cudaGetSymbolAddress((void**)&cs,     g_cs);
    cudaGetSymbolAddress((void**)&state2, g_state2);
    cudaGetSymbolAddress((void**)&a0hi,   g_A0hi);
    cudaGetSymbolAddress((void**)&a0lo,   g_A0lo);
    cudaGetSymbolAddress((void**)&a1hi,   g_A1hi);
    cudaGetSymbolAddress((void**)&a1lo,   g_A1lo);
    cudaGetSymbolAddress((void**)&wshi,   g_Wshi);
    cudaGetSymbolAddress((void**)&wslo,   g_Wslo);
    cudaGetSymbolAddress((void**)&vhi,    g_Vhi);
    cudaGetSymbolAddress((void**)&vlo,    g_Vlo);

    const size_t SBYTES = (size_t)EHq * ROWS * sizeof(float);
    cudaMemsetAsync(state2, 0, (size_t)ROWS * Dq * sizeof(float));

    k_embed<<<ROWS / 16, 128>>>(nodes, Wemb, bemb, a0hi, a0lo);

    // ---- layer 0 ----
    k_split_w<<<(EHq * 128 * 128 / 4) / 256, 256>>>(W0, wshi, wslo);
    cudaMemsetAsync(s1, 0, SBYTES);
    cudaMemsetAsync(s2, 0, SBYTES);
    cudaMemsetAsync(cs, 0, SBYTES);
    k_gemm_wh<128><<<dim3(ROWS / 64, EHq), 256>>>(a0hi, a0lo, wshi, wslo,
                                                  vhi, vlo, A1w0, A2w0, s1, s2);
    k_colsum<<<dim3(Nq / 128, Bq, 32), 128>>>(edges, s1, s2, A1b0, A2b0, cs);
    k_lncs<<<(EHq * ROWS) / 256, 256>>>(cs);
    k_msg<0><<<dim3(Nq / 64, Bq, EHq), 256>>>(edges, s1, s2, A1b0, A2b0, cs,
                                              vhi, vlo, SB0,
                                              nullptr, a1hi, a1lo);

    // ---- layer 1 ----
    k_split_w<<<(EHq * 512 * 128 / 4) / 256, 256>>>(W1, wshi, wslo);
    cudaMemsetAsync(s1, 0, SBYTES);
    cudaMemsetAsync(s2, 0, SBYTES);
    cudaMemsetAsync(cs, 0, SBYTES);
    k_gemm_wh<512><<<dim3(ROWS / 64, EHq), 256>>>(a1hi, a1lo, wshi, wslo,
                                                  vhi, vlo, A1w1, A2w1, s1, s2);
    k_colsum<<<dim3(Nq / 128, Bq, 32), 128>>>(edges, s1, s2, A1b1, A2b1, cs);
    k_lncs<<<(EHq * ROWS) / 256, 256>>>(cs);
    k_msg<1><<<dim3(Nq / 64, Bq, EHq), 256>>>(edges, s1, s2, A1b1, A2b1, cs,
                                              vhi, vlo, SB1,
                                              state2, nullptr, nullptr);

    k_out<<<ROWS / 32, 256>>>(state2, Wout, bout, (float*)d_out);
}